// round 1
// baseline (speedup 1.0000x reference)
#include <cuda_runtime.h>
#include <math.h>
#include <stdint.h>

#define B_ROWS 65536
#define S_DIM  376
#define A_DIM  17
#define H1_DIM 400
#define H2_DIM 300
#define K_FLOWS 15
#define HEAD_N 559   // 17 mu + 17 lv + 255 u + 255 w + 15 b

// ---------------- scratch (static device globals; no allocation) -------------
__device__ float g_h1[(size_t)B_ROWS * H1_DIM];     // 104.9 MB
__device__ float g_h2[(size_t)B_ROWS * H2_DIM];     //  78.6 MB
__device__ float g_heads[(size_t)B_ROWS * HEAD_N];  // 146.6 MB
__device__ float g_Wh[H2_DIM * HEAD_N];
__device__ float g_bh[HEAD_N];

// ---------------- pack the 5 head weight matrices into one [300,559] ---------
__global__ void pack_heads(const float* __restrict__ Wmu, const float* __restrict__ bmu,
                           const float* __restrict__ Wlv, const float* __restrict__ blv,
                           const float* __restrict__ Wu,  const float* __restrict__ bu,
                           const float* __restrict__ Ww,  const float* __restrict__ bw,
                           const float* __restrict__ Wb,  const float* __restrict__ bb)
{
    int idx = blockIdx.x * blockDim.x + threadIdx.x;
    const int total = H2_DIM * HEAD_N;
    if (idx < total) {
        int r = idx / HEAD_N;
        int c = idx - r * HEAD_N;
        float v;
        if      (c < 17)  v = Wmu[r * 17  + c];
        else if (c < 34)  v = Wlv[r * 17  + (c - 34 + 17)];
        else if (c < 289) v = Wu [r * 255 + (c - 34)];
        else if (c < 544) v = Ww [r * 255 + (c - 289)];
        else              v = Wb [r * 15  + (c - 544)];
        g_Wh[idx] = v;
    }
    if (idx < HEAD_N) {
        int c = idx;
        float v;
        if      (c < 17)  v = bmu[c];
        else if (c < 34)  v = blv[c - 17];
        else if (c < 289) v = bu [c - 34];
        else if (c < 544) v = bw [c - 289];
        else              v = bb [c - 544];
        g_bh[c] = v;
    }
}

// ---------------- fp32 tiled GEMM: Y = act(X[M,K] @ W[K,N] + bias) -----------
// Block tile 128(M) x 64(N), K-tile 4. 256 threads, each computes 8x4.
template <int RELU>
__global__ __launch_bounds__(256) void gemm_bias(
    const float* __restrict__ X, const float* __restrict__ W,
    const float* __restrict__ bias, float* __restrict__ Y,
    int M, int Kd, int N)
{
    __shared__ float As[4][128];
    __shared__ float Bs[4][64];

    const int tid = threadIdx.x;
    const int tx = tid & 15;        // 0..15 -> 4 cols each
    const int ty = tid >> 4;        // 0..15 -> 8 rows each
    const int m0 = blockIdx.y * 128;
    const int n0 = blockIdx.x * 64;

    float acc[8][4];
#pragma unroll
    for (int i = 0; i < 8; i++)
#pragma unroll
        for (int j = 0; j < 4; j++) acc[i][j] = 0.0f;

    for (int k0 = 0; k0 < Kd; k0 += 4) {
        if (tid < 128) {
            // one float4 per row of A (Kd is a multiple of 4 for all layers)
            float4 a = *reinterpret_cast<const float4*>(X + (size_t)(m0 + tid) * Kd + k0);
            As[0][tid] = a.x; As[1][tid] = a.y; As[2][tid] = a.z; As[3][tid] = a.w;
        } else if (tid < 192) {
            int t  = tid - 128;       // 0..63
            int kk = t >> 4;          // 0..3
            int j  = (t & 15) * 4;    // 0..60
            const float* wr = W + (size_t)(k0 + kk) * N;
#pragma unroll
            for (int q = 0; q < 4; q++) {
                int col = n0 + j + q;
                Bs[kk][j + q] = (col < N) ? wr[col] : 0.0f;
            }
        }
        __syncthreads();

#pragma unroll
        for (int kk = 0; kk < 4; kk++) {
            float a[8], b[4];
            float4 a0 = *reinterpret_cast<const float4*>(&As[kk][ty * 8]);
            float4 a1 = *reinterpret_cast<const float4*>(&As[kk][ty * 8 + 4]);
            a[0]=a0.x; a[1]=a0.y; a[2]=a0.z; a[3]=a0.w;
            a[4]=a1.x; a[5]=a1.y; a[6]=a1.z; a[7]=a1.w;
            float4 b0 = *reinterpret_cast<const float4*>(&Bs[kk][tx * 4]);
            b[0]=b0.x; b[1]=b0.y; b[2]=b0.z; b[3]=b0.w;
#pragma unroll
            for (int i = 0; i < 8; i++)
#pragma unroll
                for (int j = 0; j < 4; j++)
                    acc[i][j] = fmaf(a[i], b[j], acc[i][j]);
        }
        __syncthreads();
    }

#pragma unroll
    for (int i = 0; i < 8; i++) {
        int row = m0 + ty * 8 + i;   // M is a multiple of 128
        float* yr = Y + (size_t)row * N;
#pragma unroll
        for (int j = 0; j < 4; j++) {
            int col = n0 + tx * 4 + j;
            if (col < N) {
                float v = acc[i][j] + bias[col];
                if (RELU) v = fmaxf(v, 0.0f);
                yr[col] = v;
            }
        }
    }
}

// ---------------- flow chain + sampling + log-prob epilogue ------------------
// One warp per batch row. Lane a (<17) owns action component a.
__global__ __launch_bounds__(256) void flow_kernel(
    const float* __restrict__ eps, float* __restrict__ out)
{
    const int warp = (blockIdx.x * blockDim.x + threadIdx.x) >> 5;
    const int lane = threadIdx.x & 31;
    if (warp >= B_ROWS) return;

    const float* hr = g_heads + (size_t)warp * HEAD_N;
    const bool act = (lane < A_DIM);

    float mu = 0.0f, lv = 0.0f, e = 0.0f;
    if (act) {
        mu = tanhf(hr[lane]);            // MAX_ACTION = 1
        lv = tanhf(hr[17 + lane]);
        e  = eps[(size_t)warp * A_DIM + lane];
    }
    float z = mu + expf(lv) * e;         // rsample
    float ldj = 0.0f;

    for (int k = 0; k < K_FLOWS; k++) {
        float u = 0.0f, w = 0.0f;
        if (act) {
            u = hr[34  + k * A_DIM + lane];
            w = hr[289 + k * A_DIM + lane];
        }
        float bk = hr[544 + k];

        float uw  = w * u;
        float wns = w * w;
        float wz  = w * z;
#pragma unroll
        for (int s = 16; s; s >>= 1) {
            uw  += __shfl_xor_sync(0xffffffffu, uw,  s);
            wns += __shfl_xor_sync(0xffffffffu, wns, s);
            wz  += __shfl_xor_sync(0xffffffffu, wz,  s);
        }
        // softplus, numerically stable
        float sp   = fmaxf(uw, 0.0f) + log1pf(expf(-fabsf(uw)));
        float m_uw = -1.0f + sp;
        float scale = (m_uw - uw) / wns;
        float u_hat = u + scale * w;
        float t = tanhf(wz + bk);
        z += u_hat * t;
        // w . u_hat == m_uw analytically
        float psi_u = m_uw * (1.0f - t * t);
        ldj += logf(fabsf(1.0f + psi_u));
    }

    if (act) out[(size_t)warp * A_DIM + lane] = z;

    float lp = act ? (-0.5f * e * e - lv) : 0.0f;
#pragma unroll
    for (int s = 16; s; s >>= 1) lp += __shfl_xor_sync(0xffffffffu, lp, s);
    lp -= 0.5f * (float)A_DIM * 1.8378770664093453f;   // log(2*pi)

    if (lane == 0) {
        float lpf = lp - ldj;
        out[(size_t)B_ROWS * A_DIM + warp]          = expf(lpf);
        out[(size_t)B_ROWS * A_DIM + B_ROWS + warp] = lpf;
    }
}

// ---------------- launch ------------------------------------------------------
extern "C" void kernel_launch(void* const* d_in, const int* in_sizes, int n_in,
                              void* d_out, int out_size)
{
    (void)in_sizes; (void)n_in; (void)out_size;

    const float* x   = (const float*)d_in[0];
    const float* eps = (const float*)d_in[1];
    const float* W1  = (const float*)d_in[2];
    const float* b1  = (const float*)d_in[3];
    const float* W2  = (const float*)d_in[4];
    const float* b2  = (const float*)d_in[5];
    const float* Wmu = (const float*)d_in[6];
    const float* bmu = (const float*)d_in[7];
    const float* Wlv = (const float*)d_in[8];
    const float* blv = (const float*)d_in[9];
    const float* Wu  = (const float*)d_in[10];
    const float* bu  = (const float*)d_in[11];
    const float* Ww  = (const float*)d_in[12];
    const float* bw  = (const float*)d_in[13];
    const float* Wb  = (const float*)d_in[14];
    const float* bb  = (const float*)d_in[15];
    float* out = (float*)d_out;

    float *h1p, *h2p, *hdp, *whp, *bhp;
    cudaGetSymbolAddress((void**)&h1p, g_h1);
    cudaGetSymbolAddress((void**)&h2p, g_h2);
    cudaGetSymbolAddress((void**)&hdp, g_heads);
    cudaGetSymbolAddress((void**)&whp, g_Wh);
    cudaGetSymbolAddress((void**)&bhp, g_bh);

    // pack head weights: 300*559 = 167700 elements
    pack_heads<<<(H2_DIM * HEAD_N + 255) / 256, 256>>>(Wmu, bmu, Wlv, blv,
                                                       Wu, bu, Ww, bw, Wb, bb);

    dim3 blk(256);
    dim3 g1((H1_DIM + 63) / 64, B_ROWS / 128);
    gemm_bias<1><<<g1, blk>>>(x, W1, b1, h1p, B_ROWS, S_DIM, H1_DIM);

    dim3 g2((H2_DIM + 63) / 64, B_ROWS / 128);
    gemm_bias<1><<<g2, blk>>>(h1p, W2, b2, h2p, B_ROWS, H1_DIM, H2_DIM);

    dim3 g3((HEAD_N + 63) / 64, B_ROWS / 128);
    gemm_bias<0><<<g3, blk>>>(h2p, whp, bhp, hdp, B_ROWS, H2_DIM, HEAD_N);

    flow_kernel<<<(B_ROWS * 32) / 256, 256>>>(eps, out);
}

// round 2
// speedup vs baseline: 2.6113x; 2.6113x over previous
#include <cuda_runtime.h>
#include <cuda_bf16.h>
#include <math.h>
#include <stdint.h>

#define B_ROWS 65536
#define S_DIM  376
#define A_DIM  17
#define H1_DIM 400
#define H2_DIM 300
#define K_FLOWS 15
#define HEAD_N 559

// padded dims (K padded to mult of 32, N padded to mult of 64)
#define KP0 384   // padded S_DIM
#define NB1 448   // padded H1_DIM  (= K of layer 2)
#define KP1 448
#define NB2 320   // padded H2_DIM  (= K of layer 3)
#define KP2 320
#define NB3 576   // padded HEAD_N

// ---------------- scratch (static device globals; no allocation) -------------
__device__ __nv_bfloat16 g_xhi[(size_t)B_ROWS * KP0];
__device__ __nv_bfloat16 g_xlo[(size_t)B_ROWS * KP0];
__device__ __nv_bfloat16 g_h1hi[(size_t)B_ROWS * NB1];
__device__ __nv_bfloat16 g_h1lo[(size_t)B_ROWS * NB1];
__device__ __nv_bfloat16 g_h2hi[(size_t)B_ROWS * NB2];
__device__ __nv_bfloat16 g_h2lo[(size_t)B_ROWS * NB2];
__device__ float         g_heads[(size_t)B_ROWS * NB3];

__device__ __nv_bfloat16 g_W1hi[KP0 * NB1], g_W1lo[KP0 * NB1];
__device__ __nv_bfloat16 g_W2hi[KP1 * NB2], g_W2lo[KP1 * NB2];
__device__ __nv_bfloat16 g_Whhi[KP2 * NB3], g_Whlo[KP2 * NB3];
__device__ float         g_bh[HEAD_N];

// ---------------- small helpers ----------------------------------------------
__device__ __forceinline__ uint32_t smem_u32(const void* p) {
    return (uint32_t)__cvta_generic_to_shared(p);
}
__device__ __forceinline__ void cp16(uint32_t dst, const void* src) {
    asm volatile("cp.async.cg.shared.global [%0], [%1], 16;\n" :: "r"(dst), "l"(src));
}
__device__ __forceinline__ void cp_commit() {
    asm volatile("cp.async.commit_group;\n" ::);
}
__device__ __forceinline__ void cp_wait1() {
    asm volatile("cp.async.wait_group 1;\n" ::);
}
__device__ __forceinline__ void ldsm_x4(uint32_t* r, uint32_t addr) {
    asm volatile("ldmatrix.sync.aligned.m8n8.x4.shared.b16 {%0,%1,%2,%3}, [%4];\n"
                 : "=r"(r[0]), "=r"(r[1]), "=r"(r[2]), "=r"(r[3]) : "r"(addr));
}
__device__ __forceinline__ void ldsm_x4t(uint32_t* r, uint32_t addr) {
    asm volatile("ldmatrix.sync.aligned.m8n8.x4.trans.shared.b16 {%0,%1,%2,%3}, [%4];\n"
                 : "=r"(r[0]), "=r"(r[1]), "=r"(r[2]), "=r"(r[3]) : "r"(addr));
}
__device__ __forceinline__ void mma16816(float* c, const uint32_t* a, uint32_t b0, uint32_t b1) {
    asm volatile("mma.sync.aligned.m16n8k16.row.col.f32.bf16.bf16.f32 "
                 "{%0,%1,%2,%3}, {%4,%5,%6,%7}, {%8,%9}, {%0,%1,%2,%3};\n"
                 : "+f"(c[0]), "+f"(c[1]), "+f"(c[2]), "+f"(c[3])
                 : "r"(a[0]), "r"(a[1]), "r"(a[2]), "r"(a[3]), "r"(b0), "r"(b1));
}

// ---------------- conversion / packing kernels --------------------------------
__global__ void convert_x(const float* __restrict__ x,
                          __nv_bfloat16* __restrict__ hi, __nv_bfloat16* __restrict__ lo)
{
    size_t idx = (size_t)blockIdx.x * blockDim.x + threadIdx.x;
    if (idx >= (size_t)B_ROWS * KP0) return;
    int m = (int)(idx / KP0);
    int k = (int)(idx - (size_t)m * KP0);
    float v = (k < S_DIM) ? x[(size_t)m * S_DIM + k] : 0.0f;
    __nv_bfloat16 h = __float2bfloat16(v);
    hi[idx] = h;
    lo[idx] = __float2bfloat16(v - __bfloat162float(h));
}

__global__ void convert_w(const float* __restrict__ W, int K, int N,
                          __nv_bfloat16* __restrict__ hi, __nv_bfloat16* __restrict__ lo,
                          int KPd, int NBd)
{
    int idx = blockIdx.x * blockDim.x + threadIdx.x;
    if (idx >= KPd * NBd) return;
    int k = idx / NBd, n = idx - k * NBd;
    float v = (k < K && n < N) ? W[(size_t)k * N + n] : 0.0f;
    __nv_bfloat16 h = __float2bfloat16(v);
    hi[idx] = h;
    lo[idx] = __float2bfloat16(v - __bfloat162float(h));
}

__global__ void pack_heads(const float* __restrict__ Wmu, const float* __restrict__ bmu,
                           const float* __restrict__ Wlv, const float* __restrict__ blv,
                           const float* __restrict__ Wu,  const float* __restrict__ bu,
                           const float* __restrict__ Ww,  const float* __restrict__ bw,
                           const float* __restrict__ Wb,  const float* __restrict__ bb)
{
    int idx = blockIdx.x * blockDim.x + threadIdx.x;
    if (idx < KP2 * NB3) {
        int k = idx / NB3, c = idx - k * NB3;
        float v = 0.0f;
        if (k < H2_DIM) {
            if      (c < 17)  v = Wmu[k * 17  + c];
            else if (c < 34)  v = Wlv[k * 17  + (c - 17)];
            else if (c < 289) v = Wu [k * 255 + (c - 34)];
            else if (c < 544) v = Ww [k * 255 + (c - 289)];
            else if (c < 559) v = Wb [k * 15  + (c - 544)];
        }
        __nv_bfloat16 h = __float2bfloat16(v);
        g_Whhi[idx] = h;
        g_Whlo[idx] = __float2bfloat16(v - __bfloat162float(h));
    }
    if (idx < HEAD_N) {
        int c = idx;
        float v;
        if      (c < 17)  v = bmu[c];
        else if (c < 34)  v = blv[c - 17];
        else if (c < 289) v = bu [c - 34];
        else if (c < 544) v = bw [c - 289];
        else              v = bb [c - 544];
        g_bh[c] = v;
    }
}

// ---------------- tensor-core GEMM --------------------------------------------
// C[M x NB] = op( A @ B + bias ), A given as (hi, lo) bf16 row-major [M x lda],
// B as (hi, lo) bf16 row-major [lda x ldb] (zero-padded). 2-term split:
//   acc = Ahi*Bhi + Ahi*Blo + Alo*Bhi.
// OUT==1: relu + split to (Chi, Clo) with zero padding beyond N.
// OUT==0: fp32 out (bias added; pad cols naturally 0).
// Block tile 128(M) x 64(N) x 32(K), 256 threads, 2-stage cp.async pipeline.
template <int OUT>
__global__ __launch_bounds__(256, 2) void gemm_mma(
    const __nv_bfloat16* __restrict__ Ahi, const __nv_bfloat16* __restrict__ Alo, int lda,
    const __nv_bfloat16* __restrict__ Bhi, const __nv_bfloat16* __restrict__ Blo, int ldb,
    const float* __restrict__ bias, int N,
    float* __restrict__ Cf,
    __nv_bfloat16* __restrict__ Chi, __nv_bfloat16* __restrict__ Clo, int ldc)
{
    // As: 128 rows x 64 cols (cols 0-31 = hi k-tile, 32-63 = lo k-tile), row = 128B
    // Bs: 32 rows  x 128 cols (cols 0-63 = hi n-tile, 64-127 = lo n-tile), row = 256B
    __shared__ __nv_bfloat16 As[2][128][64];
    __shared__ __nv_bfloat16 Bs[2][32][128];

    const int tid  = threadIdx.x;
    const int lane = tid & 31;
    const int wid  = tid >> 5;
    const int wm   = wid & 3;      // 4 warps over M (32 rows each)
    const int wn   = wid >> 2;     // 2 warps over N (32 cols each)
    const int m0   = blockIdx.y * 128;
    const int n0   = blockIdx.x * 64;
    const int KT   = lda / 32;

    float acc[2][4][4];
#pragma unroll
    for (int i = 0; i < 2; i++)
#pragma unroll
        for (int j = 0; j < 4; j++)
#pragma unroll
            for (int q = 0; q < 4; q++) acc[i][j][q] = 0.0f;

    auto loadA = [&](int st, int kt) {
#pragma unroll
        for (int q = 0; q < 4; q++) {
            int g   = tid + 256 * q;           // 0..1023 chunks of 16B
            int row = g >> 3;
            int c8  = g & 7;                   // 0-3: hi, 4-7: lo
            const __nv_bfloat16* src =
                (c8 < 4 ? Ahi : Alo) + (size_t)(m0 + row) * lda + kt * 32 + (c8 & 3) * 8;
            cp16(smem_u32(&As[st][row][((c8 ^ row) & 7) * 8]), src);
        }
    };
    auto loadB = [&](int st, int kt) {
#pragma unroll
        for (int q = 0; q < 2; q++) {
            int g   = tid + 256 * q;           // 0..511
            int row = g >> 4;
            int c16 = g & 15;                  // 0-7: hi, 8-15: lo
            const __nv_bfloat16* src =
                (c16 < 8 ? Bhi : Blo) + (size_t)(kt * 32 + row) * ldb + n0 + (c16 & 7) * 8;
            int phys = (c16 & 8) | ((c16 ^ row) & 7);
            cp16(smem_u32(&Bs[st][row][phys * 8]), src);
        }
    };

    loadA(0, 0); loadB(0, 0); cp_commit();

    for (int kt = 0; kt < KT; kt++) {
        int st = kt & 1;
        if (kt + 1 < KT) { loadA(st ^ 1, kt + 1); loadB(st ^ 1, kt + 1); }
        cp_commit();
        cp_wait1();
        __syncthreads();

#pragma unroll
        for (int kk = 0; kk < 2; kk++) {
            uint32_t ah[2][4], al[2][4], bh[2][4], bl[2][4];
            // A fragments: rows wm*32 + mi*16 + lane%16, k-half by lane/16
            {
                int row = (lane & 15);
                int half = (lane >> 4);
#pragma unroll
                for (int mi = 0; mi < 2; mi++) {
                    int r = wm * 32 + mi * 16 + row;
                    int c8h = kk * 2 + half;           // hi
                    int c8l = 4 + kk * 2 + half;       // lo
                    ldsm_x4(ah[mi], smem_u32(&As[st][r][((c8h ^ r) & 7) * 8]));
                    ldsm_x4(al[mi], smem_u32(&As[st][r][((c8l ^ r) & 7) * 8]));
                }
            }
            // B fragments: rows kk*16 + lane%16, col group by lane/16 (.trans)
            {
                int row = kk * 16 + (lane & 15);
                int half = (lane >> 4);
#pragma unroll
                for (int ni = 0; ni < 2; ni++) {
                    int c16h = wn * 4 + ni * 2 + half;        // hi (0..7)
                    int c16l = 8 + wn * 4 + ni * 2 + half;    // lo (8..15)
                    int ph = (c16h & 8) | ((c16h ^ row) & 7);
                    int pl = (c16l & 8) | ((c16l ^ row) & 7);
                    ldsm_x4t(bh[ni], smem_u32(&Bs[st][row][ph * 8]));
                    ldsm_x4t(bl[ni], smem_u32(&Bs[st][row][pl * 8]));
                }
            }
#pragma unroll
            for (int mi = 0; mi < 2; mi++) {
#pragma unroll
                for (int n8 = 0; n8 < 4; n8++) {
                    int ni = n8 >> 1, j = (n8 & 1) * 2;
                    mma16816(acc[mi][n8], ah[mi], bh[ni][j], bh[ni][j + 1]); // hi*hi
                    mma16816(acc[mi][n8], ah[mi], bl[ni][j], bl[ni][j + 1]); // hi*lo
                    mma16816(acc[mi][n8], al[mi], bh[ni][j], bh[ni][j + 1]); // lo*hi
                }
            }
        }
        __syncthreads();
    }

    // ---- epilogue ----
    const int lr = lane >> 2;          // 0..7
    const int lc = (lane & 3) * 2;     // 0,2,4,6
#pragma unroll
    for (int mi = 0; mi < 2; mi++) {
#pragma unroll
        for (int n8 = 0; n8 < 4; n8++) {
            int col = n0 + wn * 32 + n8 * 8 + lc;
            float b0 = (col     < N) ? bias[col]     : 0.0f;
            float b1 = (col + 1 < N) ? bias[col + 1] : 0.0f;
#pragma unroll
            for (int h = 0; h < 2; h++) {
                int row = m0 + wm * 32 + mi * 16 + h * 8 + lr;
                float v0 = acc[mi][n8][2 * h + 0] + b0;
                float v1 = acc[mi][n8][2 * h + 1] + b1;
                if (OUT == 1) {
                    v0 = (col     < N) ? fmaxf(v0, 0.0f) : 0.0f;
                    v1 = (col + 1 < N) ? fmaxf(v1, 0.0f) : 0.0f;
                    __nv_bfloat16 h0 = __float2bfloat16(v0);
                    __nv_bfloat16 h1 = __float2bfloat16(v1);
                    __nv_bfloat162 hp; hp.x = h0; hp.y = h1;
                    __nv_bfloat162 lp;
                    lp.x = __float2bfloat16(v0 - __bfloat162float(h0));
                    lp.y = __float2bfloat16(v1 - __bfloat162float(h1));
                    *reinterpret_cast<__nv_bfloat162*>(&Chi[(size_t)row * ldc + col]) = hp;
                    *reinterpret_cast<__nv_bfloat162*>(&Clo[(size_t)row * ldc + col]) = lp;
                } else {
                    float2 f2; f2.x = v0; f2.y = v1;
                    *reinterpret_cast<float2*>(&Cf[(size_t)row * ldc + col]) = f2;
                }
            }
        }
    }
}

// ---------------- flow chain + sampling + log-prob epilogue ------------------
__global__ __launch_bounds__(256) void flow_kernel(
    const float* __restrict__ eps, float* __restrict__ out)
{
    const int warp = (blockIdx.x * blockDim.x + threadIdx.x) >> 5;
    const int lane = threadIdx.x & 31;
    if (warp >= B_ROWS) return;

    const float* hr = g_heads + (size_t)warp * NB3;
    const bool act = (lane < A_DIM);

    float mu = 0.0f, lv = 0.0f, e = 0.0f;
    if (act) {
        mu = tanhf(hr[lane]);
        lv = tanhf(hr[17 + lane]);
        e  = eps[(size_t)warp * A_DIM + lane];
    }
    float z = mu + expf(lv) * e;
    float ldj = 0.0f;

    for (int k = 0; k < K_FLOWS; k++) {
        float u = 0.0f, w = 0.0f;
        if (act) {
            u = hr[34  + k * A_DIM + lane];
            w = hr[289 + k * A_DIM + lane];
        }
        float bk = hr[544 + k];

        float uw  = w * u;
        float wns = w * w;
        float wz  = w * z;
#pragma unroll
        for (int s = 16; s; s >>= 1) {
            uw  += __shfl_xor_sync(0xffffffffu, uw,  s);
            wns += __shfl_xor_sync(0xffffffffu, wns, s);
            wz  += __shfl_xor_sync(0xffffffffu, wz,  s);
        }
        float sp   = fmaxf(uw, 0.0f) + log1pf(expf(-fabsf(uw)));
        float m_uw = -1.0f + sp;
        float scale = (m_uw - uw) / wns;
        float u_hat = u + scale * w;
        float t = tanhf(wz + bk);
        z += u_hat * t;
        float psi_u = m_uw * (1.0f - t * t);
        ldj += logf(fabsf(1.0f + psi_u));
    }

    if (act) out[(size_t)warp * A_DIM + lane] = z;

    float lp = act ? (-0.5f * e * e - lv) : 0.0f;
#pragma unroll
    for (int s = 16; s; s >>= 1) lp += __shfl_xor_sync(0xffffffffu, lp, s);
    lp -= 0.5f * (float)A_DIM * 1.8378770664093453f;

    if (lane == 0) {
        float lpf = lp - ldj;
        out[(size_t)B_ROWS * A_DIM + warp]          = expf(lpf);
        out[(size_t)B_ROWS * A_DIM + B_ROWS + warp] = lpf;
    }
}

// ---------------- launch ------------------------------------------------------
extern "C" void kernel_launch(void* const* d_in, const int* in_sizes, int n_in,
                              void* d_out, int out_size)
{
    (void)in_sizes; (void)n_in; (void)out_size;

    const float* x   = (const float*)d_in[0];
    const float* eps = (const float*)d_in[1];
    const float* W1  = (const float*)d_in[2];
    const float* b1  = (const float*)d_in[3];
    const float* W2  = (const float*)d_in[4];
    const float* b2  = (const float*)d_in[5];
    const float* Wmu = (const float*)d_in[6];
    const float* bmu = (const float*)d_in[7];
    const float* Wlv = (const float*)d_in[8];
    const float* blv = (const float*)d_in[9];
    const float* Wu  = (const float*)d_in[10];
    const float* bu  = (const float*)d_in[11];
    const float* Ww  = (const float*)d_in[12];
    const float* bw  = (const float*)d_in[13];
    const float* Wb  = (const float*)d_in[14];
    const float* bb  = (const float*)d_in[15];
    float* out = (float*)d_out;

    __nv_bfloat16 *xhi, *xlo, *h1hi, *h1lo, *h2hi, *h2lo;
    __nv_bfloat16 *w1hi, *w1lo, *w2hi, *w2lo, *whhi, *whlo;
    float *hdp, *bhp;
    cudaGetSymbolAddress((void**)&xhi,  g_xhi);
    cudaGetSymbolAddress((void**)&xlo,  g_xlo);
    cudaGetSymbolAddress((void**)&h1hi, g_h1hi);
    cudaGetSymbolAddress((void**)&h1lo, g_h1lo);
    cudaGetSymbolAddress((void**)&h2hi, g_h2hi);
    cudaGetSymbolAddress((void**)&h2lo, g_h2lo);
    cudaGetSymbolAddress((void**)&w1hi, g_W1hi);
    cudaGetSymbolAddress((void**)&w1lo, g_W1lo);
    cudaGetSymbolAddress((void**)&w2hi, g_W2hi);
    cudaGetSymbolAddress((void**)&w2lo, g_W2lo);
    cudaGetSymbolAddress((void**)&whhi, g_Whhi);
    cudaGetSymbolAddress((void**)&whlo, g_Whlo);
    cudaGetSymbolAddress((void**)&hdp,  g_heads);
    cudaGetSymbolAddress((void**)&bhp,  g_bh);

    // conversions / packing (weights tiny; x is ~100MB of traffic)
    convert_x<<<(int)(((size_t)B_ROWS * KP0 + 255) / 256), 256>>>(x, xhi, xlo);
    convert_w<<<(KP0 * NB1 + 255) / 256, 256>>>(W1, S_DIM,  H1_DIM, w1hi, w1lo, KP0, NB1);
    convert_w<<<(KP1 * NB2 + 255) / 256, 256>>>(W2, H1_DIM, H2_DIM, w2hi, w2lo, KP1, NB2);
    pack_heads<<<(KP2 * NB3 + 255) / 256, 256>>>(Wmu, bmu, Wlv, blv, Wu, bu, Ww, bw, Wb, bb);

    dim3 blk(256);
    // layer 1: [65536,384] x [384,448] -> h1 (relu, split), real N=400
    gemm_mma<1><<<dim3(NB1 / 64, B_ROWS / 128), blk>>>(
        xhi, xlo, KP0, w1hi, w1lo, NB1, b1, H1_DIM,
        nullptr, h1hi, h1lo, NB1);
    // layer 2: [65536,448] x [448,320] -> h2 (relu, split), real N=300
    gemm_mma<1><<<dim3(NB2 / 64, B_ROWS / 128), blk>>>(
        h1hi, h1lo, KP1, w2hi, w2lo, NB2, b2, H2_DIM,
        nullptr, h2hi, h2lo, NB2);
    // heads: [65536,320] x [320,576] -> fp32, real N=559
    gemm_mma<0><<<dim3(NB3 / 64, B_ROWS / 128), blk>>>(
        h2hi, h2lo, KP2, whhi, whlo, NB3, bhp, HEAD_N,
        hdp, nullptr, nullptr, NB3);

    flow_kernel<<<(B_ROWS * 32) / 256, 256>>>(eps, out);
}